// round 4
// baseline (speedup 1.0000x reference)
#include <cuda_runtime.h>
#include <cuda_bf16.h>
#include <math.h>

// Problem constants
#define BB   16
#define HH   16
#define LL   2048
#define DK   64
#define LK   4096
#define CC   10
#define LKS  16
#define NBH  (BB*HH)                 // 256
#define CTX_ELEMS ((size_t)BB*HH*LL*DK)   // 33,554,432

// ---------------- scratch (static device arrays; no cudaMalloc allowed) ----
__device__ float g_Ks[NBH*LKS*DK];          // (b,h,s,d) 262144
__device__ float g_Vs[NBH*LKS*DK];
__device__ float g_cq[NBH*LKS*DK*CC];       // (b,h,s,d,c) 2,621,440
__device__ float g_A [NBH*LKS*DK*CC];       // one-hot-masked q_mean
__device__ double g_lp_sum;
__device__ double g_ce_sum;

// ---------------------------------------------------------------- reset ----
__global__ void reset_kernel() {
    g_lp_sum = 0.0;
    g_ce_sum = 0.0;
}

// ----------------------------------------------------------- 1) shrink -----
// Ks[bh,s,d] = sum_k K[bh,k,d]*wk[s,k] + bk[s]   (same for V)
// block = 256 threads: thread (s0=tid>>6 in 0..3, d=tid&63) computes
// s in {s0, s0+4, s0+8, s0+12} for both K and V. Chunk of 8 k at a time,
// W held in registers (float4 loads) -> FMA:LDS ~ 2:1.
__global__ void __launch_bounds__(256) shrink_kernel(
    const float* __restrict__ K, const float* __restrict__ V,
    const float* __restrict__ wk, const float* __restrict__ bk,
    const float* __restrict__ wv, const float* __restrict__ bv)
{
    __shared__ float Kt[8*64];
    __shared__ float Vt[8*64];
    __shared__ float Wks[16*8];
    __shared__ float Wvs[16*8];

    int bh  = blockIdx.x;
    int tid = threadIdx.x;
    int d   = tid & 63;
    int s0  = tid >> 6;          // 0..3

    float accK[4] = {0.f,0.f,0.f,0.f};
    float accV[4] = {0.f,0.f,0.f,0.f};

    const float4* Kg = (const float4*)(K + (size_t)bh * LK * DK);
    const float4* Vg = (const float4*)(V + (size_t)bh * LK * DK);

    for (int c = 0; c < LK/8; c++) {
        if (tid < 128) {
            ((float4*)Kt)[tid] = Kg[c*128 + tid];
            int s = tid >> 3, kk = tid & 7;
            Wks[tid] = wk[s*LK + c*8 + kk];
        } else {
            int t = tid - 128;
            ((float4*)Vt)[t] = Vg[c*128 + t];
            int s = t >> 3, kk = t & 7;
            Wvs[t] = wv[s*LK + c*8 + kk];
        }
        __syncthreads();

        float wkr[4][8], wvr[4][8];
        #pragma unroll
        for (int ss = 0; ss < 4; ss++) {
            int s = s0 + ss*4;
            float4 a  = ((const float4*)Wks)[s*2];
            float4 b2 = ((const float4*)Wks)[s*2+1];
            wkr[ss][0]=a.x; wkr[ss][1]=a.y; wkr[ss][2]=a.z; wkr[ss][3]=a.w;
            wkr[ss][4]=b2.x; wkr[ss][5]=b2.y; wkr[ss][6]=b2.z; wkr[ss][7]=b2.w;
            float4 c1 = ((const float4*)Wvs)[s*2];
            float4 c2 = ((const float4*)Wvs)[s*2+1];
            wvr[ss][0]=c1.x; wvr[ss][1]=c1.y; wvr[ss][2]=c1.z; wvr[ss][3]=c1.w;
            wvr[ss][4]=c2.x; wvr[ss][5]=c2.y; wvr[ss][6]=c2.z; wvr[ss][7]=c2.w;
        }
        #pragma unroll
        for (int kk = 0; kk < 8; kk++) {
            float kv = Kt[kk*64 + d];
            float vv = Vt[kk*64 + d];
            #pragma unroll
            for (int ss = 0; ss < 4; ss++) {
                accK[ss] += kv * wkr[ss][kk];
                accV[ss] += vv * wvr[ss][kk];
            }
        }
        __syncthreads();
    }
    #pragma unroll
    for (int ss = 0; ss < 4; ss++) {
        int s = s0 + ss*4;
        g_Ks[((size_t)bh*LKS + s)*DK + d] = accK[ss] + bk[s];
        g_Vs[((size_t)bh*LKS + s)*DK + d] = accV[ss] + bv[s];
    }
}

// ------------------------------------------------------ 2) cluster MLPs ----
// one thread per (b,h,s,d). Emits cluster_q (for CE) and A (masked q_mean),
// accumulates sum(log_prob).
__global__ void __launch_bounds__(256) cluster_kernel(
    const float* __restrict__ pw,  const float* __restrict__ pb,
    const float* __restrict__ ckw, const float* __restrict__ ckb,
    const float* __restrict__ cqw, const float* __restrict__ cqb,
    const float* __restrict__ muw, const float* __restrict__ mub,
    const float* __restrict__ sgw, const float* __restrict__ sgb)
{
    __shared__ float s_pw[160], s_ckw[100], s_cqw[100], s_muw[100], s_sgw[100];
    __shared__ float s_pb[10], s_ckb[10], s_cqb[10], s_mub[10], s_sgb[10];
    __shared__ float s_red[256];

    int tid = threadIdx.x;
    if (tid < 160) s_pw[tid] = pw[tid];
    if (tid < 100) { s_ckw[tid]=ckw[tid]; s_cqw[tid]=cqw[tid];
                     s_muw[tid]=muw[tid]; s_sgw[tid]=sgw[tid]; }
    if (tid < 10)  { s_pb[tid]=pb[tid]; s_ckb[tid]=ckb[tid]; s_cqb[tid]=cqb[tid];
                     s_mub[tid]=mub[tid]; s_sgb[tid]=sgb[tid]; }
    __syncthreads();

    int idx = blockIdx.x*256 + tid;      // < 262144
    int d  = idx & 63;
    int s  = (idx >> 6) & 15;
    int h  = (idx >> 10) & 15;
    int bb = idx >> 14;

    // unfold window over batch dim
    float v[16];
    #pragma unroll
    for (int j = 0; j < 16; j++) {
        int m = bb + j;
        v[j] = (m >= 16) ? g_Ks[((((m-15)*HH + h)*LKS + s)*DK) + d] : 0.f;
    }

    float p[10];
    #pragma unroll
    for (int c = 0; c < 10; c++) {
        float a = s_pb[c];
        #pragma unroll
        for (int j = 0; j < 16; j++) a += v[j]*s_pw[c*16+j];
        p[c] = fmaxf(a, 0.f);
    }

    float kl[10], ql[10];
    #pragma unroll
    for (int c = 0; c < 10; c++) {
        float a = s_ckb[c], b2 = s_cqb[c];
        #pragma unroll
        for (int c2 = 0; c2 < 10; c2++) {
            a  += p[c2]*s_ckw[c*10+c2];
            b2 += p[c2]*s_cqw[c*10+c2];
        }
        kl[c] = a; ql[c] = b2;
    }

    // argmax of cluster_q == argmax of logits (monotone); first-max like jnp
    int amax = 0; { float best = ql[0];
        #pragma unroll
        for (int c = 1; c < 10; c++) if (ql[c] > best) { best = ql[c]; amax = c; } }

    // softmax both
    float mk = kl[0], mq = ql[0];
    #pragma unroll
    for (int c = 1; c < 10; c++) { mk = fmaxf(mk, kl[c]); mq = fmaxf(mq, ql[c]); }
    float sk = 0.f, sq = 0.f;
    #pragma unroll
    for (int c = 0; c < 10; c++) { kl[c] = expf(kl[c]-mk); sk += kl[c];
                                   ql[c] = expf(ql[c]-mq); sq += ql[c]; }
    float ik = 1.f/sk, iq = 1.f/sq;
    #pragma unroll
    for (int c = 0; c < 10; c++) { kl[c] *= ik; ql[c] *= iq; }

    // mu / sigma / log_prob
    float lp_local = 0.f;
    #pragma unroll
    for (int c = 0; c < 10; c++) {
        float mu = s_mub[c], sg = s_sgb[c];
        #pragma unroll
        for (int c2 = 0; c2 < 10; c2++) {
            mu += ql[c2]*s_muw[c*10+c2];
            sg += ql[c2]*s_sgw[c*10+c2];
        }
        float sigma = (sg > 20.f) ? sg : log1pf(expf(sg));   // softplus
        float t = (kl[c] - mu) / sigma;
        lp_local += -0.5f*t*t - logf(sigma) - 0.91893853320467274f;
    }

    // stores
    float qmean = 0.f;
    #pragma unroll
    for (int c = 0; c < 10; c++) qmean += ql[c];
    qmean *= 0.1f;
    size_t base = (size_t)idx * 10;
    #pragma unroll
    for (int c = 0; c < 10; c++) {
        g_cq[base + c] = ql[c];
        g_A [base + c] = (c == amax) ? qmean : 0.f;
    }

    // block-reduce log_prob sum
    s_red[tid] = lp_local;
    __syncthreads();
    for (int off = 128; off > 0; off >>= 1) {
        if (tid < off) s_red[tid] += s_red[tid+off];
        __syncthreads();
    }
    if (tid == 0) atomicAdd(&g_lp_sum, (double)s_red[0]);
}

// --------------------------------------------------------------- 3) CE -----
// ce_sum += sum over (b,s,d,c) of sum_h q[h]*(q[h]-logsumexp_h(q))
__global__ void __launch_bounds__(256) ce_kernel()
{
    __shared__ float s_red[256];
    int tid = threadIdx.x;
    int i = blockIdx.x*256 + tid;       // < 163840
    int c = i % 10;
    int rest = i / 10;
    int d  = rest & 63;
    int s  = (rest >> 6) & 15;
    int bb = rest >> 10;

    float x[16];
    size_t base = ((((size_t)bb*HH)*LKS + s)*DK + d)*10 + c;
    #pragma unroll
    for (int h = 0; h < 16; h++) x[h] = g_cq[base + (size_t)h*LKS*DK*10];
    float m = x[0];
    #pragma unroll
    for (int h = 1; h < 16; h++) m = fmaxf(m, x[h]);
    float sum = 0.f;
    #pragma unroll
    for (int h = 0; h < 16; h++) sum += expf(x[h]-m);
    float lse = m + logf(sum);
    float acc = 0.f;
    #pragma unroll
    for (int h = 0; h < 16; h++) acc += x[h]*(x[h]-lse);

    s_red[tid] = acc;
    __syncthreads();
    for (int off = 128; off > 0; off >>= 1) {
        if (tid < off) s_red[tid] += s_red[tid+off];
        __syncthreads();
    }
    if (tid == 0) atomicAdd(&g_ce_sum, (double)s_red[0]);
}

// --------------------------------------------------------- 4) finalize -----
__global__ void finalize_kernel(float* out, long long out_size)
{
    // loss = -mean(log_prob) + (-mean(sum_h q*logp))
    double loss = -(g_lp_sum / 2621440.0) - (g_ce_sum / 163840.0);
    for (long long k = (long long)CTX_ELEMS; k < out_size; k++)
        out[k] = (float)loss;
}

// -------------------------------------------------------- 5) attention -----
// per (bh, 128-q tile): scores = Q(128x64) @ A(64x160), max over C,
// softmax over s(16), ctx = attn @ Vs. Padded smem strides kill conflicts.
#define AS_STRIDE 645    // 64*10 + 5  (odd mod 32 -> conflict-free across s)
#define QS_STRIDE 65
__global__ void __launch_bounds__(256) attn_kernel(
    const float* __restrict__ Q, float* __restrict__ out)
{
    extern __shared__ float sm[];
    float* As  = sm;                               // 16*645 = 10320
    float* Qs  = sm + 16*AS_STRIDE;                // 128*65 = 8320
    float* Vss = Qs + 128*QS_STRIDE;               // 1024
    float* sc  = Vss + 1024;                       // 128*16 = 2048

    int bh  = blockIdx.y;
    int q0  = blockIdx.x * 128;
    int tid = threadIdx.x;

    for (int i = tid; i < LKS*DK*CC; i += 256) {
        int s = i / 640; int r = i - s*640;
        As[s*AS_STRIDE + r] = g_A[(size_t)bh*10240 + i];
    }
    const float* Qg = Q + ((size_t)bh*LL + q0)*DK;
    for (int i = tid; i < 128*64; i += 256) {
        int q = i >> 6; int d = i & 63;
        Qs[q*QS_STRIDE + d] = Qg[i];
    }
    for (int i = tid; i < LKS*DK; i += 256) Vss[i] = g_Vs[(size_t)bh*1024 + i];
    __syncthreads();

    int s = tid & 15;        // key position
    int g = tid >> 4;        // q group of 8

    float part[80];
    #pragma unroll
    for (int i = 0; i < 80; i++) part[i] = 0.f;

    for (int d = 0; d < 64; d++) {
        float qv[8];
        #pragma unroll
        for (int r = 0; r < 8; r++) qv[r] = Qs[(g*8 + r)*QS_STRIDE + d];
        #pragma unroll
        for (int c = 0; c < 10; c++) {
            float a = As[s*AS_STRIDE + d*10 + c];
            #pragma unroll
            for (int r = 0; r < 8; r++) part[r*10 + c] += qv[r]*a;
        }
    }
    #pragma unroll
    for (int r = 0; r < 8; r++) {
        float m = part[r*10];
        #pragma unroll
        for (int c = 1; c < 10; c++) m = fmaxf(m, part[r*10 + c]);
        sc[(g*8 + r)*16 + s] = m;
    }
    __syncthreads();

    if (tid < 128) {
        int q = tid;
        float m = sc[q*16];
        #pragma unroll
        for (int ss = 1; ss < 16; ss++) m = fmaxf(m, sc[q*16+ss]);
        float sum = 0.f;
        #pragma unroll
        for (int ss = 0; ss < 16; ss++) {
            float e = expf(sc[q*16+ss] - m);
            sc[q*16+ss] = e; sum += e;
        }
        float inv = 1.f/sum;
        #pragma unroll
        for (int ss = 0; ss < 16; ss++) sc[q*16+ss] *= inv;
    }
    __syncthreads();

    for (int o = tid; o < 128*64; o += 256) {
        int q = o >> 6, d = o & 63;
        float a = 0.f;
        #pragma unroll
        for (int ss = 0; ss < 16; ss++) a += sc[q*16+ss]*Vss[ss*64+d];
        out[((size_t)bh*LL + q0 + q)*DK + d] = a;
    }
}

// ---------------------------------------------------------------------------
extern "C" void kernel_launch(void* const* d_in, const int* in_sizes, int n_in,
                              void* d_out, int out_size)
{
    const float* Q   = (const float*)d_in[0];
    const float* K   = (const float*)d_in[1];
    const float* V   = (const float*)d_in[2];
    const float* skw = (const float*)d_in[3];
    const float* skb = (const float*)d_in[4];
    const float* svw = (const float*)d_in[5];
    const float* svb = (const float*)d_in[6];
    const float* pw  = (const float*)d_in[7];
    const float* pb  = (const float*)d_in[8];
    const float* ckw = (const float*)d_in[9];
    const float* ckb = (const float*)d_in[10];
    const float* cqw = (const float*)d_in[11];
    const float* cqb = (const float*)d_in[12];
    const float* muw = (const float*)d_in[13];
    const float* mub = (const float*)d_in[14];
    const float* sgw = (const float*)d_in[15];
    const float* sgb = (const float*)d_in[16];
    float* out = (float*)d_out;

    // opt-in >48KB dynamic smem for attention kernel (idempotent, not a stream op)
    cudaFuncSetAttribute(attn_kernel, cudaFuncAttributeMaxDynamicSharedMemorySize,
                         (16*AS_STRIDE + 128*QS_STRIDE + 1024 + 2048) * sizeof(float));

    reset_kernel<<<1, 1>>>();
    shrink_kernel<<<NBH, 256>>>(K, V, skw, skb, svw, svb);
    cluster_kernel<<<(NBH*LKS*DK)/256, 256>>>(pw, pb, ckw, ckb, cqw, cqb,
                                              muw, mub, sgw, sgb);
    ce_kernel<<<(BB*LKS*DK*CC)/256, 256>>>();
    finalize_kernel<<<1, 1>>>(out, (long long)out_size);
    dim3 grid(LL/128, NBH);
    size_t smem = (16*AS_STRIDE + 128*QS_STRIDE + 1024 + 2048) * sizeof(float);
    attn_kernel<<<grid, 256, smem>>>(Q, out);
}

// round 5
// speedup vs baseline: 1.2662x; 1.2662x over previous
#include <cuda_runtime.h>
#include <cuda_bf16.h>
#include <math.h>

// Problem constants
#define BB   16
#define HH   16
#define LL   2048
#define DK   64
#define LK   4096
#define CC   10
#define LKS  16
#define NBH  (BB*HH)                 // 256
#define CTX_ELEMS ((size_t)BB*HH*LL*DK)   // 33,554,432

// ---------------- scratch (static device arrays; no cudaMalloc allowed) ----
__device__ float g_Ks[NBH*LKS*DK];          // (b,h,s,d) 262144
__device__ float g_Vs[NBH*LKS*DK];
__device__ float g_cq[NBH*LKS*DK*CC];       // (b,h,s,d,c) 2,621,440
__device__ unsigned char g_amax[NBH*LKS*DK]; // argmax cluster per (b,h,s,d)
__device__ double g_lp_sum;
__device__ double g_ce_sum;

// ---------------------------------------------------------------- reset ----
__global__ void reset_kernel() {
    g_lp_sum = 0.0;
    g_ce_sum = 0.0;
}

// ----------------------------------------------------------- 1) shrink -----
// Ks[bh,s,d] = sum_k K[bh,k,d]*wk[s,k] + bk[s]   (same for V)
__global__ void __launch_bounds__(256) shrink_kernel(
    const float* __restrict__ K, const float* __restrict__ V,
    const float* __restrict__ wk, const float* __restrict__ bk,
    const float* __restrict__ wv, const float* __restrict__ bv)
{
    __shared__ float Kt[8*64];
    __shared__ float Vt[8*64];
    __shared__ float Wks[16*8];
    __shared__ float Wvs[16*8];

    int bh  = blockIdx.x;
    int tid = threadIdx.x;
    int d   = tid & 63;
    int s0  = tid >> 6;          // 0..3

    float accK[4] = {0.f,0.f,0.f,0.f};
    float accV[4] = {0.f,0.f,0.f,0.f};

    const float4* Kg = (const float4*)(K + (size_t)bh * LK * DK);
    const float4* Vg = (const float4*)(V + (size_t)bh * LK * DK);

    for (int c = 0; c < LK/8; c++) {
        if (tid < 128) {
            ((float4*)Kt)[tid] = Kg[c*128 + tid];
            int s = tid >> 3, kk = tid & 7;
            Wks[tid] = wk[s*LK + c*8 + kk];
        } else {
            int t = tid - 128;
            ((float4*)Vt)[t] = Vg[c*128 + t];
            int s = t >> 3, kk = t & 7;
            Wvs[t] = wv[s*LK + c*8 + kk];
        }
        __syncthreads();

        float wkr[4][8], wvr[4][8];
        #pragma unroll
        for (int ss = 0; ss < 4; ss++) {
            int s = s0 + ss*4;
            float4 a  = ((const float4*)Wks)[s*2];
            float4 b2 = ((const float4*)Wks)[s*2+1];
            wkr[ss][0]=a.x; wkr[ss][1]=a.y; wkr[ss][2]=a.z; wkr[ss][3]=a.w;
            wkr[ss][4]=b2.x; wkr[ss][5]=b2.y; wkr[ss][6]=b2.z; wkr[ss][7]=b2.w;
            float4 c1 = ((const float4*)Wvs)[s*2];
            float4 c2 = ((const float4*)Wvs)[s*2+1];
            wvr[ss][0]=c1.x; wvr[ss][1]=c1.y; wvr[ss][2]=c1.z; wvr[ss][3]=c1.w;
            wvr[ss][4]=c2.x; wvr[ss][5]=c2.y; wvr[ss][6]=c2.z; wvr[ss][7]=c2.w;
        }
        #pragma unroll
        for (int kk = 0; kk < 8; kk++) {
            float kv = Kt[kk*64 + d];
            float vv = Vt[kk*64 + d];
            #pragma unroll
            for (int ss = 0; ss < 4; ss++) {
                accK[ss] += kv * wkr[ss][kk];
                accV[ss] += vv * wvr[ss][kk];
            }
        }
        __syncthreads();
    }
    #pragma unroll
    for (int ss = 0; ss < 4; ss++) {
        int s = s0 + ss*4;
        g_Ks[((size_t)bh*LKS + s)*DK + d] = accK[ss] + bk[s];
        g_Vs[((size_t)bh*LKS + s)*DK + d] = accV[ss] + bv[s];
    }
}

// ------------------------------------------------------ 2) cluster MLPs ----
// one thread per (b,h,s,d). Emits cluster_q (for CE) and argmax (for attn),
// accumulates sum(log_prob).
__global__ void __launch_bounds__(256) cluster_kernel(
    const float* __restrict__ pw,  const float* __restrict__ pb,
    const float* __restrict__ ckw, const float* __restrict__ ckb,
    const float* __restrict__ cqw, const float* __restrict__ cqb,
    const float* __restrict__ muw, const float* __restrict__ mub,
    const float* __restrict__ sgw, const float* __restrict__ sgb)
{
    __shared__ float s_pw[160], s_ckw[100], s_cqw[100], s_muw[100], s_sgw[100];
    __shared__ float s_pb[10], s_ckb[10], s_cqb[10], s_mub[10], s_sgb[10];
    __shared__ float s_red[256];

    int tid = threadIdx.x;
    if (tid < 160) s_pw[tid] = pw[tid];
    if (tid < 100) { s_ckw[tid]=ckw[tid]; s_cqw[tid]=cqw[tid];
                     s_muw[tid]=muw[tid]; s_sgw[tid]=sgw[tid]; }
    if (tid < 10)  { s_pb[tid]=pb[tid]; s_ckb[tid]=ckb[tid]; s_cqb[tid]=cqb[tid];
                     s_mub[tid]=mub[tid]; s_sgb[tid]=sgb[tid]; }
    __syncthreads();

    int idx = blockIdx.x*256 + tid;      // < 262144
    int d  = idx & 63;
    int s  = (idx >> 6) & 15;
    int h  = (idx >> 10) & 15;
    int bb = idx >> 14;

    // unfold window over batch dim
    float v[16];
    #pragma unroll
    for (int j = 0; j < 16; j++) {
        int m = bb + j;
        v[j] = (m >= 16) ? g_Ks[((((m-15)*HH + h)*LKS + s)*DK) + d] : 0.f;
    }

    float p[10];
    #pragma unroll
    for (int c = 0; c < 10; c++) {
        float a = s_pb[c];
        #pragma unroll
        for (int j = 0; j < 16; j++) a += v[j]*s_pw[c*16+j];
        p[c] = fmaxf(a, 0.f);
    }

    float kl[10], ql[10];
    #pragma unroll
    for (int c = 0; c < 10; c++) {
        float a = s_ckb[c], b2 = s_cqb[c];
        #pragma unroll
        for (int c2 = 0; c2 < 10; c2++) {
            a  += p[c2]*s_ckw[c*10+c2];
            b2 += p[c2]*s_cqw[c*10+c2];
        }
        kl[c] = a; ql[c] = b2;
    }

    // argmax of cluster_q == argmax of logits (monotone); first-max like jnp
    int amax = 0; { float best = ql[0];
        #pragma unroll
        for (int c = 1; c < 10; c++) if (ql[c] > best) { best = ql[c]; amax = c; } }

    // softmax both
    float mk = kl[0], mq = ql[0];
    #pragma unroll
    for (int c = 1; c < 10; c++) { mk = fmaxf(mk, kl[c]); mq = fmaxf(mq, ql[c]); }
    float sk = 0.f, sq = 0.f;
    #pragma unroll
    for (int c = 0; c < 10; c++) { kl[c] = expf(kl[c]-mk); sk += kl[c];
                                   ql[c] = expf(ql[c]-mq); sq += ql[c]; }
    float ik = 1.f/sk, iq = 1.f/sq;
    #pragma unroll
    for (int c = 0; c < 10; c++) { kl[c] *= ik; ql[c] *= iq; }

    // mu / sigma / log_prob
    float lp_local = 0.f;
    #pragma unroll
    for (int c = 0; c < 10; c++) {
        float mu = s_mub[c], sg = s_sgb[c];
        #pragma unroll
        for (int c2 = 0; c2 < 10; c2++) {
            mu += ql[c2]*s_muw[c*10+c2];
            sg += ql[c2]*s_sgw[c*10+c2];
        }
        float sigma = (sg > 20.f) ? sg : log1pf(expf(sg));   // softplus
        float t = (kl[c] - mu) / sigma;
        lp_local += -0.5f*t*t - logf(sigma) - 0.91893853320467274f;
    }

    // stores: cluster_q for CE, argmax index for attention
    size_t base = (size_t)idx * 10;
    #pragma unroll
    for (int c = 0; c < 10; c++) g_cq[base + c] = ql[c];
    g_amax[idx] = (unsigned char)amax;

    // block-reduce log_prob sum
    s_red[tid] = lp_local;
    __syncthreads();
    for (int off = 128; off > 0; off >>= 1) {
        if (tid < off) s_red[tid] += s_red[tid+off];
        __syncthreads();
    }
    if (tid == 0) atomicAdd(&g_lp_sum, (double)s_red[0]);
}

// --------------------------------------------------------------- 3) CE -----
__global__ void __launch_bounds__(256) ce_kernel()
{
    __shared__ float s_red[256];
    int tid = threadIdx.x;
    int i = blockIdx.x*256 + tid;       // < 163840
    int c = i % 10;
    int rest = i / 10;
    int d  = rest & 63;
    int s  = (rest >> 6) & 15;
    int bb = rest >> 10;

    float x[16];
    size_t base = ((((size_t)bb*HH)*LKS + s)*DK + d)*10 + c;
    #pragma unroll
    for (int h = 0; h < 16; h++) x[h] = g_cq[base + (size_t)h*LKS*DK*10];
    float m = x[0];
    #pragma unroll
    for (int h = 1; h < 16; h++) m = fmaxf(m, x[h]);
    float sum = 0.f;
    #pragma unroll
    for (int h = 0; h < 16; h++) sum += expf(x[h]-m);
    float lse = m + logf(sum);
    float acc = 0.f;
    #pragma unroll
    for (int h = 0; h < 16; h++) acc += x[h]*(x[h]-lse);

    s_red[tid] = acc;
    __syncthreads();
    for (int off = 128; off > 0; off >>= 1) {
        if (tid < off) s_red[tid] += s_red[tid+off];
        __syncthreads();
    }
    if (tid == 0) atomicAdd(&g_ce_sum, (double)s_red[0]);
}

// --------------------------------------------------------- 4) finalize -----
__global__ void finalize_kernel(float* out, long long out_size)
{
    double loss = -(g_lp_sum / 2621440.0) - (g_ce_sum / 163840.0);
    for (long long k = (long long)CTX_ELEMS; k < out_size; k++)
        out[k] = (float)loss;
}

// -------------------------------------------------------- 5) attention -----
// q_mean == 0.1 exactly (mean of a softmax), so
//   scores[c,q,s] = 0.1 * sum_{d: argmax(s,d)=c} Q[q,d]
// Per block (bh, 128-q tile): counting-sort d by cluster per s, then warp-per-s
// segmented sums of Q columns (uniform bounds -> no divergence), max over
// segments (empty cluster contributes exactly 0), softmax over s, attn @ Vs.
#define QS_STRIDE 65   // odd -> conflict-free column gather
#define SC_STRIDE 17   // odd -> conflict-free score writes
__global__ void __launch_bounds__(256) attn_kernel(
    const float* __restrict__ Q, float* __restrict__ out)
{
    __shared__ float Qs[128*QS_STRIDE];          // 33280 f
    __shared__ float Vss[16*64];                 // 1024 f
    __shared__ float sc[128*SC_STRIDE];          // 2176 f
    __shared__ unsigned char s_perm[16][64];
    __shared__ short s_cnt[16][10];
    __shared__ short s_pos[16][10];
    __shared__ unsigned char s_empty[16];

    int bh  = blockIdx.y;
    int q0  = blockIdx.x * 128;
    int tid = threadIdx.x;

    // load Q tile (coalesced float4 from gmem, scalar stores into padded smem)
    const float* Qg = Q + ((size_t)bh*LL + q0)*DK;
    for (int i = tid; i < 128*16; i += 256) {
        int q = i >> 4, dv = i & 15;
        float4 v = ((const float4*)Qg)[i];
        float* dst = &Qs[q*QS_STRIDE + dv*4];
        dst[0]=v.x; dst[1]=v.y; dst[2]=v.z; dst[3]=v.w;
    }
    for (int i = tid; i < 16*64; i += 256) Vss[i] = g_Vs[(size_t)bh*1024 + i];

    // per-s counting sort of d by cluster (threads 0..15, serial, tiny)
    if (tid < 16) {
        int s = tid;
        const unsigned char* am = &g_amax[(size_t)bh*1024 + s*64];
        for (int c = 0; c < 10; c++) s_cnt[s][c] = 0;
        for (int d = 0; d < 64; d++) s_cnt[s][am[d]]++;
        short acc = 0; unsigned char emp = 0;
        for (int c = 0; c < 10; c++) {
            s_pos[s][c] = acc;
            acc += s_cnt[s][c];
            if (s_cnt[s][c] == 0) emp = 1;
        }
        s_empty[s] = emp;
        for (int d = 0; d < 64; d++) {
            int c = am[d];
            s_perm[s][s_pos[s][c]++] = (unsigned char)d;
        }
    }
    __syncthreads();

    // warp per s (each warp does s=wid and s=wid+8); lane handles 4 q rows
    int wid = tid >> 5, lane = tid & 31;
    #pragma unroll
    for (int si = 0; si < 2; si++) {
        int s = wid + si*8;
        float m0=-1e30f, m1=-1e30f, m2=-1e30f, m3=-1e30f;
        int pos = 0;
        for (int c = 0; c < 10; c++) {
            int n = s_cnt[s][c];
            if (n == 0) continue;
            float a0=0.f, a1=0.f, a2=0.f, a3=0.f;
            for (int j = 0; j < n; j++) {
                int d = s_perm[s][pos + j];
                a0 += Qs[(lane     )*QS_STRIDE + d];
                a1 += Qs[(lane + 32)*QS_STRIDE + d];
                a2 += Qs[(lane + 64)*QS_STRIDE + d];
                a3 += Qs[(lane + 96)*QS_STRIDE + d];
            }
            pos += n;
            m0 = fmaxf(m0, a0); m1 = fmaxf(m1, a1);
            m2 = fmaxf(m2, a2); m3 = fmaxf(m3, a3);
        }
        if (s_empty[s]) {
            m0 = fmaxf(m0, 0.f); m1 = fmaxf(m1, 0.f);
            m2 = fmaxf(m2, 0.f); m3 = fmaxf(m3, 0.f);
        }
        sc[(lane     )*SC_STRIDE + s] = 0.1f*m0;
        sc[(lane + 32)*SC_STRIDE + s] = 0.1f*m1;
        sc[(lane + 64)*SC_STRIDE + s] = 0.1f*m2;
        sc[(lane + 96)*SC_STRIDE + s] = 0.1f*m3;
    }
    __syncthreads();

    // softmax over s per q
    if (tid < 128) {
        int q = tid;
        float m = sc[q*SC_STRIDE];
        #pragma unroll
        for (int ss = 1; ss < 16; ss++) m = fmaxf(m, sc[q*SC_STRIDE+ss]);
        float sum = 0.f;
        #pragma unroll
        for (int ss = 0; ss < 16; ss++) {
            float e = expf(sc[q*SC_STRIDE+ss] - m);
            sc[q*SC_STRIDE+ss] = e; sum += e;
        }
        float inv = 1.f/sum;
        #pragma unroll
        for (int ss = 0; ss < 16; ss++) sc[q*SC_STRIDE+ss] *= inv;
    }
    __syncthreads();

    // context = attn @ Vs
    for (int o = tid; o < 128*64; o += 256) {
        int q = o >> 6, d = o & 63;
        float a = 0.f;
        #pragma unroll
        for (int ss = 0; ss < 16; ss++) a += sc[q*SC_STRIDE+ss]*Vss[ss*64+d];
        out[((size_t)bh*LL + q0 + q)*DK + d] = a;
    }
}

// ---------------------------------------------------------------------------
extern "C" void kernel_launch(void* const* d_in, const int* in_sizes, int n_in,
                              void* d_out, int out_size)
{
    const float* Q   = (const float*)d_in[0];
    const float* K   = (const float*)d_in[1];
    const float* V   = (const float*)d_in[2];
    const float* skw = (const float*)d_in[3];
    const float* skb = (const float*)d_in[4];
    const float* svw = (const float*)d_in[5];
    const float* svb = (const float*)d_in[6];
    const float* pw  = (const float*)d_in[7];
    const float* pb  = (const float*)d_in[8];
    const float* ckw = (const float*)d_in[9];
    const float* ckb = (const float*)d_in[10];
    const float* cqw = (const float*)d_in[11];
    const float* cqb = (const float*)d_in[12];
    const float* muw = (const float*)d_in[13];
    const float* mub = (const float*)d_in[14];
    const float* sgw = (const float*)d_in[15];
    const float* sgb = (const float*)d_in[16];
    float* out = (float*)d_out;

    reset_kernel<<<1, 1>>>();
    shrink_kernel<<<NBH, 256>>>(K, V, skw, skb, svw, svb);
    cluster_kernel<<<(NBH*LKS*DK)/256, 256>>>(pw, pb, ckw, ckb, cqw, cqb,
                                              muw, mub, sgw, sgb);
    ce_kernel<<<(BB*LKS*DK*CC)/256, 256>>>();
    finalize_kernel<<<1, 1>>>(out, (long long)out_size);
    dim3 grid(LL/128, NBH);
    attn_kernel<<<grid, 256>>>(Q, out);
}

// round 6
// speedup vs baseline: 1.6495x; 1.3027x over previous
#include <cuda_runtime.h>
#include <cuda_bf16.h>
#include <math.h>

// Problem constants
#define BB   16
#define HH   16
#define LL   2048
#define DK   64
#define LK   4096
#define CC   10
#define LKS  16
#define NBH  (BB*HH)                 // 256
#define CTX_ELEMS ((size_t)BB*HH*LL*DK)   // 33,554,432

#define KSPLIT 2
#define KSEG   (LK/KSPLIT)           // 2048
#define SCH    32                    // k per chunk
#define NCH    (KSEG/SCH)            // 64

// ---------------- scratch (static device arrays; no cudaMalloc allowed) ----
__device__ float g_Ks[NBH*LKS*DK];            // (b,h,s,d)
__device__ float g_Vs[NBH*LKS*DK];
__device__ float g_KsP[KSPLIT][NBH*LKS*DK];   // k-split partials
__device__ float g_VsP[KSPLIT][NBH*LKS*DK];
__device__ float g_cq[NBH*LKS*DK*CC];         // (b,h,s,d,c)
__device__ unsigned char g_amax[NBH*LKS*DK];
__device__ double g_lp_sum;
__device__ double g_ce_sum;

// ---------------------------------------------------------------- reset ----
__global__ void reset_kernel() {
    g_lp_sum = 0.0;
    g_ce_sum = 0.0;
}

// ----------------------------------------------------------- 1) shrink -----
// Partial: g_KsP[seg][bh,s,d] = sum_{k in seg} K[bh,k,d]*wk[s,k]  (same V)
// Block (bh, seg): 256 thr = 16 s x 16 dgroups(4d). Double-buffered smem
// staging with register prefetch -> gmem latency hidden; 64 barriers total.
__global__ void __launch_bounds__(256) shrink_kernel(
    const float* __restrict__ K, const float* __restrict__ V,
    const float* __restrict__ wk, const float* __restrict__ wv)
{
    __shared__ float Kc[2][SCH][64];     // 16 KB
    __shared__ float Vc[2][SCH][64];     // 16 KB
    __shared__ float Wk[2][16][SCH];     // 4 KB
    __shared__ float Wv[2][16][SCH];     // 4 KB

    int bh  = blockIdx.x;
    int seg = blockIdx.y;
    int tid = threadIdx.x;
    int dg  = tid & 15;       // d-group (4 d)
    int s   = tid >> 4;       // 0..15

    const float* Kg = K + ((size_t)bh*LK + (size_t)seg*KSEG)*DK;
    const float* Vg = V + ((size_t)bh*LK + (size_t)seg*KSEG)*DK;
    const float* wkr = wk + (size_t)s*LK + seg*KSEG;
    const float* wvr = wv + (size_t)s*LK + seg*KSEG;

    // tile-load decomposition: float4 f = tid and tid+256
    int kkl = tid >> 4;       // 0..15  (row for first float4)
    int dcl = tid & 15;       // 0..15  (16B column)

    float4 pK0, pK1, pV0, pV1; float2 pwk, pwv;

    // prefetch chunk c into registers
    #define PREFETCH(cbase) do {                                         \
        pK0 = *(const float4*)(Kg + (size_t)((cbase)+kkl   )*64 + dcl*4);\
        pK1 = *(const float4*)(Kg + (size_t)((cbase)+kkl+16)*64 + dcl*4);\
        pV0 = *(const float4*)(Vg + (size_t)((cbase)+kkl   )*64 + dcl*4);\
        pV1 = *(const float4*)(Vg + (size_t)((cbase)+kkl+16)*64 + dcl*4);\
        pwk = *(const float2*)(wkr + (cbase) + dg*2);                    \
        pwv = *(const float2*)(wvr + (cbase) + dg*2);                    \
    } while(0)

    #define STORECHUNK(b) do {                                           \
        *(float4*)&Kc[b][kkl   ][dcl*4] = pK0;                           \
        *(float4*)&Kc[b][kkl+16][dcl*4] = pK1;                           \
        *(float4*)&Vc[b][kkl   ][dcl*4] = pV0;                           \
        *(float4*)&Vc[b][kkl+16][dcl*4] = pV1;                           \
        Wk[b][s][dg*2]   = pwk.x;  Wk[b][s][dg*2+1] = pwk.y;             \
        Wv[b][s][dg*2]   = pwv.x;  Wv[b][s][dg*2+1] = pwv.y;             \
    } while(0)

    PREFETCH(0);
    STORECHUNK(0);
    __syncthreads();

    float4 aK = make_float4(0.f,0.f,0.f,0.f);
    float4 aV = make_float4(0.f,0.f,0.f,0.f);

    for (int c = 0; c < NCH; c++) {
        int b = c & 1;
        if (c + 1 < NCH) PREFETCH((c+1)*SCH);

        #pragma unroll
        for (int k4 = 0; k4 < SCH/4; k4++) {
            float4 wkq = *(float4*)&Wk[b][s][k4*4];
            float4 wvq = *(float4*)&Wv[b][s][k4*4];
            #pragma unroll
            for (int j = 0; j < 4; j++) {
                float4 kq = *(float4*)&Kc[b][k4*4+j][dg*4];
                float4 vq = *(float4*)&Vc[b][k4*4+j][dg*4];
                float wa = (&wkq.x)[j];
                float wb = (&wvq.x)[j];
                aK.x += kq.x*wa; aK.y += kq.y*wa;
                aK.z += kq.z*wa; aK.w += kq.w*wa;
                aV.x += vq.x*wb; aV.y += vq.y*wb;
                aV.z += vq.z*wb; aV.w += vq.w*wb;
            }
        }
        if (c + 1 < NCH) STORECHUNK((c+1)&1);
        __syncthreads();
    }

    int o = (bh*16 + s)*64 + dg*4;
    *(float4*)&g_KsP[seg][o] = aK;
    *(float4*)&g_VsP[seg][o] = aV;
    #undef PREFETCH
    #undef STORECHUNK
}

// deterministic partial reduction + bias
__global__ void __launch_bounds__(256) reduce_shrink_kernel(
    const float* __restrict__ bk, const float* __restrict__ bv)
{
    int i = blockIdx.x*256 + threadIdx.x;   // float4 index < 65536
    int s = ((i*4) >> 6) & 15;
    float4 k0 = ((const float4*)g_KsP[0])[i];
    float4 k1 = ((const float4*)g_KsP[1])[i];
    float4 v0 = ((const float4*)g_VsP[0])[i];
    float4 v1 = ((const float4*)g_VsP[1])[i];
    float bbk = bk[s], bbv = bv[s];
    float4 rk, rv;
    rk.x = k0.x+k1.x+bbk; rk.y = k0.y+k1.y+bbk;
    rk.z = k0.z+k1.z+bbk; rk.w = k0.w+k1.w+bbk;
    rv.x = v0.x+v1.x+bbv; rv.y = v0.y+v1.y+bbv;
    rv.z = v0.z+v1.z+bbv; rv.w = v0.w+v1.w+bbv;
    ((float4*)g_Ks)[i] = rk;
    ((float4*)g_Vs)[i] = rv;
}

// ------------------------------------------------------ 2) cluster MLPs ----
__global__ void __launch_bounds__(256) cluster_kernel(
    const float* __restrict__ pw,  const float* __restrict__ pb,
    const float* __restrict__ ckw, const float* __restrict__ ckb,
    const float* __restrict__ cqw, const float* __restrict__ cqb,
    const float* __restrict__ muw, const float* __restrict__ mub,
    const float* __restrict__ sgw, const float* __restrict__ sgb)
{
    __shared__ float s_pw[160], s_ckw[100], s_cqw[100], s_muw[100], s_sgw[100];
    __shared__ float s_pb[10], s_ckb[10], s_cqb[10], s_mub[10], s_sgb[10];
    __shared__ float s_red[256];

    int tid = threadIdx.x;
    if (tid < 160) s_pw[tid] = pw[tid];
    if (tid < 100) { s_ckw[tid]=ckw[tid]; s_cqw[tid]=cqw[tid];
                     s_muw[tid]=muw[tid]; s_sgw[tid]=sgw[tid]; }
    if (tid < 10)  { s_pb[tid]=pb[tid]; s_ckb[tid]=ckb[tid]; s_cqb[tid]=cqb[tid];
                     s_mub[tid]=mub[tid]; s_sgb[tid]=sgb[tid]; }
    __syncthreads();

    int idx = blockIdx.x*256 + tid;      // < 262144
    int d  = idx & 63;
    int s  = (idx >> 6) & 15;
    int h  = (idx >> 10) & 15;
    int bb = idx >> 14;

    float v[16];
    #pragma unroll
    for (int j = 0; j < 16; j++) {
        int m = bb + j;
        v[j] = (m >= 16) ? g_Ks[((((m-15)*HH + h)*LKS + s)*DK) + d] : 0.f;
    }

    float p[10];
    #pragma unroll
    for (int c = 0; c < 10; c++) {
        float a = s_pb[c];
        #pragma unroll
        for (int j = 0; j < 16; j++) a += v[j]*s_pw[c*16+j];
        p[c] = fmaxf(a, 0.f);
    }

    float kl[10], ql[10];
    #pragma unroll
    for (int c = 0; c < 10; c++) {
        float a = s_ckb[c], b2 = s_cqb[c];
        #pragma unroll
        for (int c2 = 0; c2 < 10; c2++) {
            a  += p[c2]*s_ckw[c*10+c2];
            b2 += p[c2]*s_cqw[c*10+c2];
        }
        kl[c] = a; ql[c] = b2;
    }

    int amax = 0; { float best = ql[0];
        #pragma unroll
        for (int c = 1; c < 10; c++) if (ql[c] > best) { best = ql[c]; amax = c; } }

    float mk = kl[0], mq = ql[0];
    #pragma unroll
    for (int c = 1; c < 10; c++) { mk = fmaxf(mk, kl[c]); mq = fmaxf(mq, ql[c]); }
    float sk = 0.f, sq = 0.f;
    #pragma unroll
    for (int c = 0; c < 10; c++) { kl[c] = expf(kl[c]-mk); sk += kl[c];
                                   ql[c] = expf(ql[c]-mq); sq += ql[c]; }
    float ik = 1.f/sk, iq = 1.f/sq;
    #pragma unroll
    for (int c = 0; c < 10; c++) { kl[c] *= ik; ql[c] *= iq; }

    float lp_local = 0.f;
    #pragma unroll
    for (int c = 0; c < 10; c++) {
        float mu = s_mub[c], sg = s_sgb[c];
        #pragma unroll
        for (int c2 = 0; c2 < 10; c2++) {
            mu += ql[c2]*s_muw[c*10+c2];
            sg += ql[c2]*s_sgw[c*10+c2];
        }
        float sigma = (sg > 20.f) ? sg : log1pf(expf(sg));   // softplus
        float t = (kl[c] - mu) / sigma;
        lp_local += -0.5f*t*t - logf(sigma) - 0.91893853320467274f;
    }

    size_t base = (size_t)idx * 10;
    #pragma unroll
    for (int c = 0; c < 10; c++) g_cq[base + c] = ql[c];
    g_amax[idx] = (unsigned char)amax;

    s_red[tid] = lp_local;
    __syncthreads();
    for (int off = 128; off > 0; off >>= 1) {
        if (tid < off) s_red[tid] += s_red[tid+off];
        __syncthreads();
    }
    if (tid == 0) atomicAdd(&g_lp_sum, (double)s_red[0]);
}

// --------------------------------------------------------------- 3) CE -----
__global__ void __launch_bounds__(256) ce_kernel()
{
    __shared__ float s_red[256];
    int tid = threadIdx.x;
    int i = blockIdx.x*256 + tid;       // < 163840
    int c = i % 10;
    int rest = i / 10;
    int d  = rest & 63;
    int s  = (rest >> 6) & 15;
    int bb = rest >> 10;

    float x[16];
    size_t base = ((((size_t)bb*HH)*LKS + s)*DK + d)*10 + c;
    #pragma unroll
    for (int h = 0; h < 16; h++) x[h] = g_cq[base + (size_t)h*LKS*DK*10];
    float m = x[0];
    #pragma unroll
    for (int h = 1; h < 16; h++) m = fmaxf(m, x[h]);
    float sum = 0.f;
    #pragma unroll
    for (int h = 0; h < 16; h++) sum += expf(x[h]-m);
    float lse = m + logf(sum);
    float acc = 0.f;
    #pragma unroll
    for (int h = 0; h < 16; h++) acc += x[h]*(x[h]-lse);

    s_red[tid] = acc;
    __syncthreads();
    for (int off = 128; off > 0; off >>= 1) {
        if (tid < off) s_red[tid] += s_red[tid+off];
        __syncthreads();
    }
    if (tid == 0) atomicAdd(&g_ce_sum, (double)s_red[0]);
}

// --------------------------------------------------------- 4) finalize -----
__global__ void finalize_kernel(float* out, long long out_size)
{
    double loss = -(g_lp_sum / 2621440.0) - (g_ce_sum / 163840.0);
    for (long long k = (long long)CTX_ELEMS; k < out_size; k++)
        out[k] = (float)loss;
}

// -------------------------------------------------------- 5) attention -----
// q_mean == 0.1 exactly, so scores[c,q,s] = 0.1 * sum_{d: argmax(s,d)=c} Q[q,d]
#define QS_STRIDE 65
#define SC_STRIDE 17
__global__ void __launch_bounds__(256) attn_kernel(
    const float* __restrict__ Q, float* __restrict__ out)
{
    __shared__ float Qs[128*QS_STRIDE];
    __shared__ float Vss[16*64];
    __shared__ float sc[128*SC_STRIDE];
    __shared__ unsigned char s_perm[16][64];
    __shared__ short s_cnt[16][10];
    __shared__ short s_pos[16][10];
    __shared__ unsigned char s_empty[16];

    int bh  = blockIdx.y;
    int q0  = blockIdx.x * 128;
    int tid = threadIdx.x;

    const float* Qg = Q + ((size_t)bh*LL + q0)*DK;
    for (int i = tid; i < 128*16; i += 256) {
        int q = i >> 4, dv = i & 15;
        float4 v = ((const float4*)Qg)[i];
        float* dst = &Qs[q*QS_STRIDE + dv*4];
        dst[0]=v.x; dst[1]=v.y; dst[2]=v.z; dst[3]=v.w;
    }
    for (int i = tid; i < 16*64; i += 256) Vss[i] = g_Vs[(size_t)bh*1024 + i];

    if (tid < 16) {
        int s = tid;
        const unsigned char* am = &g_amax[(size_t)bh*1024 + s*64];
        for (int c = 0; c < 10; c++) s_cnt[s][c] = 0;
        for (int d = 0; d < 64; d++) s_cnt[s][am[d]]++;
        short acc = 0; unsigned char emp = 0;
        for (int c = 0; c < 10; c++) {
            s_pos[s][c] = acc;
            acc += s_cnt[s][c];
            if (s_cnt[s][c] == 0) emp = 1;
        }
        s_empty[s] = emp;
        for (int d = 0; d < 64; d++) {
            int c = am[d];
            s_perm[s][s_pos[s][c]++] = (unsigned char)d;
        }
    }
    __syncthreads();

    int wid = tid >> 5, lane = tid & 31;
    #pragma unroll
    for (int si = 0; si < 2; si++) {
        int s = wid + si*8;
        float m0=-1e30f, m1=-1e30f, m2=-1e30f, m3=-1e30f;
        int pos = 0;
        for (int c = 0; c < 10; c++) {
            int n = s_cnt[s][c];
            if (n == 0) continue;
            float a0=0.f, a1=0.f, a2=0.f, a3=0.f;
            for (int j = 0; j < n; j++) {
                int d = s_perm[s][pos + j];
                a0 += Qs[(lane     )*QS_STRIDE + d];
                a1 += Qs[(lane + 32)*QS_STRIDE + d];
                a2 += Qs[(lane + 64)*QS_STRIDE + d];
                a3 += Qs[(lane + 96)*QS_STRIDE + d];
            }
            pos += n;
            m0 = fmaxf(m0, a0); m1 = fmaxf(m1, a1);
            m2 = fmaxf(m2, a2); m3 = fmaxf(m3, a3);
        }
        if (s_empty[s]) {
            m0 = fmaxf(m0, 0.f); m1 = fmaxf(m1, 0.f);
            m2 = fmaxf(m2, 0.f); m3 = fmaxf(m3, 0.f);
        }
        sc[(lane     )*SC_STRIDE + s] = 0.1f*m0;
        sc[(lane + 32)*SC_STRIDE + s] = 0.1f*m1;
        sc[(lane + 64)*SC_STRIDE + s] = 0.1f*m2;
        sc[(lane + 96)*SC_STRIDE + s] = 0.1f*m3;
    }
    __syncthreads();

    if (tid < 128) {
        int q = tid;
        float m = sc[q*SC_STRIDE];
        #pragma unroll
        for (int ss = 1; ss < 16; ss++) m = fmaxf(m, sc[q*SC_STRIDE+ss]);
        float sum = 0.f;
        #pragma unroll
        for (int ss = 0; ss < 16; ss++) {
            float e = expf(sc[q*SC_STRIDE+ss] - m);
            sc[q*SC_STRIDE+ss] = e; sum += e;
        }
        float inv = 1.f/sum;
        #pragma unroll
        for (int ss = 0; ss < 16; ss++) sc[q*SC_STRIDE+ss] *= inv;
    }
    __syncthreads();

    for (int o = tid; o < 128*64; o += 256) {
        int q = o >> 6, d = o & 63;
        float a = 0.f;
        #pragma unroll
        for (int ss = 0; ss < 16; ss++) a += sc[q*SC_STRIDE+ss]*Vss[ss*64+d];
        out[((size_t)bh*LL + q0 + q)*DK + d] = a;
    }
}

// ---------------------------------------------------------------------------
extern "C" void kernel_launch(void* const* d_in, const int* in_sizes, int n_in,
                              void* d_out, int out_size)
{
    const float* Q   = (const float*)d_in[0];
    const float* K   = (const float*)d_in[1];
    const float* V   = (const float*)d_in[2];
    const float* skw = (const float*)d_in[3];
    const float* skb = (const float*)d_in[4];
    const float* svw = (const float*)d_in[5];
    const float* svb = (const float*)d_in[6];
    const float* pw  = (const float*)d_in[7];
    const float* pb  = (const float*)d_in[8];
    const float* ckw = (const float*)d_in[9];
    const float* ckb = (const float*)d_in[10];
    const float* cqw = (const float*)d_in[11];
    const float* cqb = (const float*)d_in[12];
    const float* muw = (const float*)d_in[13];
    const float* mub = (const float*)d_in[14];
    const float* sgw = (const float*)d_in[15];
    const float* sgb = (const float*)d_in[16];
    float* out = (float*)d_out;

    reset_kernel<<<1, 1>>>();
    dim3 sg(NBH, KSPLIT);
    shrink_kernel<<<sg, 256>>>(K, V, skw, svw);
    reduce_shrink_kernel<<<256, 256>>>(skb, svb);
    cluster_kernel<<<(NBH*LKS*DK)/256, 256>>>(pw, pb, ckw, ckb, cqw, cqb,
                                              muw, mub, sgw, sgb);
    ce_kernel<<<(BB*LKS*DK*CC)/256, 256>>>();
    finalize_kernel<<<1, 1>>>(out, (long long)out_size);
    dim3 grid(LL/128, NBH);
    attn_kernel<<<grid, 256>>>(Q, out);
}